// round 2
// baseline (speedup 1.0000x reference)
#include <cuda_runtime.h>

// Problem constants
#define NBATCH 2
#define LSEQ   2048
#define EMBD   1024
#define NHEAD  16
#define HDIM   64
#define MROWS  (NBATCH * LSEQ)   // 4096

// Scratch (device globals: no allocation allowed)
__device__ float g_q[NBATCH * NHEAD * LSEQ * HDIM];
__device__ float g_k[NBATCH * NHEAD * LSEQ * HDIM];
__device__ float g_v[NBATCH * NHEAD * LSEQ * HDIM];
__device__ float g_attn[MROWS * EMBD];

__device__ __forceinline__ float red_sum16(float v) {
#pragma unroll
    for (int o = 8; o > 0; o >>= 1) v += __shfl_xor_sync(0xffffffffu, v, o, 16);
    return v;
}
__device__ __forceinline__ float red_max16(float v) {
#pragma unroll
    for (int o = 8; o > 0; o >>= 1) v = fmaxf(v, __shfl_xor_sync(0xffffffffu, v, o, 16));
    return v;
}

// C = A @ W^T.  A: [MROWS, EMBD] row-major.  W: [out=EMBD, in=EMBD] row-major.
// MODE 0: per-head LayerNorm epilogue, head-major output [N,H,L,D]
// MODE 1: head-major output [N,H,L,D], no LN
// MODE 2: row-major output [MROWS, EMBD] + bias
template <int MODE>
__global__ void __launch_bounds__(256) gemm64(
    const float* __restrict__ A, const float* __restrict__ W,
    const float* __restrict__ gamma, const float* __restrict__ beta,
    const float* __restrict__ bias, float* __restrict__ C)
{
    __shared__ float As[16][64];   // transposed: As[k][row]
    __shared__ float Ws[16][64];   // transposed: Ws[k][col]

    const int tid = threadIdx.x;
    const int ty  = tid >> 4;      // 0..15
    const int tx  = tid & 15;      // 0..15
    const int rb  = blockIdx.x * 64;
    const int cb  = blockIdx.y * 64;
    const int lrow = tid >> 2;         // 0..63
    const int lk   = (tid & 3) << 2;   // 0,4,8,12

    float acc[4][4] = {};

    const float* aptr = A + (size_t)(rb + lrow) * EMBD + lk;
    const float* wptr = W + (size_t)(cb + lrow) * EMBD + lk;

    for (int k0 = 0; k0 < EMBD; k0 += 16) {
        float4 av = *(const float4*)(aptr + k0);
        float4 wv = *(const float4*)(wptr + k0);
        __syncthreads();
        As[lk + 0][lrow] = av.x; As[lk + 1][lrow] = av.y;
        As[lk + 2][lrow] = av.z; As[lk + 3][lrow] = av.w;
        Ws[lk + 0][lrow] = wv.x; Ws[lk + 1][lrow] = wv.y;
        Ws[lk + 2][lrow] = wv.z; Ws[lk + 3][lrow] = wv.w;
        __syncthreads();
#pragma unroll
        for (int k = 0; k < 16; k++) {
            float4 a4 = *(const float4*)&As[k][ty * 4];
            float4 w4 = *(const float4*)&Ws[k][tx * 4];
            float ar[4] = {a4.x, a4.y, a4.z, a4.w};
            float wr[4] = {w4.x, w4.y, w4.z, w4.w};
#pragma unroll
            for (int i = 0; i < 4; i++)
#pragma unroll
                for (int j = 0; j < 4; j++)
                    acc[i][j] = fmaf(ar[i], wr[j], acc[i][j]);
        }
    }

    if (MODE == 0) {
        // Per-head LayerNorm: each tile row (64 cols) is exactly one head vector.
#pragma unroll
        for (int i = 0; i < 4; i++) {
            float s  = acc[i][0] + acc[i][1] + acc[i][2] + acc[i][3];
            float s2 = acc[i][0]*acc[i][0] + acc[i][1]*acc[i][1]
                     + acc[i][2]*acc[i][2] + acc[i][3]*acc[i][3];
            s  = red_sum16(s);
            s2 = red_sum16(s2);
            const float mean = s * (1.0f / 64.0f);
            const float var  = s2 * (1.0f / 64.0f) - mean * mean;
            const float rstd = rsqrtf(var + 1e-5f);
#pragma unroll
            for (int j = 0; j < 4; j++) {
                const int d = tx * 4 + j;
                acc[i][j] = (acc[i][j] - mean) * rstd * gamma[d] + beta[d];
            }
        }
    }

    if (MODE == 0 || MODE == 1) {
        const int h = blockIdx.y;  // cb/64
#pragma unroll
        for (int i = 0; i < 4; i++) {
            const int rr = rb + ty * 4 + i;
            const int n  = rr >> 11;        // /LSEQ
            const int l  = rr & (LSEQ - 1);
            float* dst = C + ((size_t)((n * NHEAD + h) * LSEQ + l)) * HDIM + tx * 4;
            *(float4*)dst = make_float4(acc[i][0], acc[i][1], acc[i][2], acc[i][3]);
        }
    } else {
        const float4 b4 = *(const float4*)&bias[cb + tx * 4];
#pragma unroll
        for (int i = 0; i < 4; i++) {
            const int rr = rb + ty * 4 + i;
            float* dst = C + (size_t)rr * EMBD + cb + tx * 4;
            *(float4*)dst = make_float4(acc[i][0] + b4.x, acc[i][1] + b4.y,
                                        acc[i][2] + b4.z, acc[i][3] + b4.w);
        }
    }
}

// Flash attention, fp32, causal. Q/K/V: [N*H, L, D] head-major.
// Output written directly in [N, L, H*D] layout for the final GEMM.
__global__ void __launch_bounds__(256) attn_kernel(
    const float* __restrict__ Q, const float* __restrict__ K,
    const float* __restrict__ V, float* __restrict__ O)
{
    __shared__ float Qs[64][64];   // [d][qrow]
    __shared__ float KVs[64][64];  // K phase: [d][krow];  V phase: [j][d]
    __shared__ float Ps[64][64];   // [qrow][j]

    const int tid = threadIdx.x;
    const int ty  = tid >> 4;
    const int tx  = tid & 15;
    const int nh  = blockIdx.y;                     // n*NHEAD + h
    const int qt  = gridDim.x - 1 - blockIdx.x;     // heavy tiles first
    const int qb  = qt * 64;
    const size_t base = (size_t)nh * LSEQ * HDIM;

    const int lrow = tid >> 2;         // 0..63 (tile row)
    const int lk   = (tid & 3) << 4;   // 0,16,32,48 (base d-chunk; each thread covers 4 f4)

    {   // Load full Q tile transposed: each thread does 4 float4 = 16 d-values
#pragma unroll
        for (int c = 0; c < 4; c++) {
            const int d0 = lk + c * 4;
            float4 qv = *(const float4*)&Q[base + (size_t)(qb + lrow) * HDIM + d0];
            Qs[d0 + 0][lrow] = qv.x; Qs[d0 + 1][lrow] = qv.y;
            Qs[d0 + 2][lrow] = qv.z; Qs[d0 + 3][lrow] = qv.w;
        }
    }

    float acc[4][4] = {};
    float mrow[4] = {-1e30f, -1e30f, -1e30f, -1e30f};
    float lsum[4] = {0.f, 0.f, 0.f, 0.f};

    for (int kt = 0; kt <= qt; kt++) {
        const int kb = kt * 64;
        float4 kv[4];
#pragma unroll
        for (int c = 0; c < 4; c++)
            kv[c] = *(const float4*)&K[base + (size_t)(kb + lrow) * HDIM + lk + c * 4];
        __syncthreads();   // prior PV reads of KVs/Ps done; Q store done (iter 0)
#pragma unroll
        for (int c = 0; c < 4; c++) {
            const int d0 = lk + c * 4;
            KVs[d0 + 0][lrow] = kv[c].x; KVs[d0 + 1][lrow] = kv[c].y;
            KVs[d0 + 2][lrow] = kv[c].z; KVs[d0 + 3][lrow] = kv[c].w;
        }
        __syncthreads();

        // S = Q K^T
        float s[4][4] = {};
#pragma unroll 8
        for (int k = 0; k < 64; k++) {
            float4 q4 = *(const float4*)&Qs[k][ty * 4];
            float4 k4 = *(const float4*)&KVs[k][tx * 4];
            float qr[4] = {q4.x, q4.y, q4.z, q4.w};
            float kr[4] = {k4.x, k4.y, k4.z, k4.w};
#pragma unroll
            for (int i = 0; i < 4; i++)
#pragma unroll
                for (int j = 0; j < 4; j++)
                    s[i][j] = fmaf(qr[i], kr[j], s[i][j]);
        }

        if (kt == qt) {   // diagonal tile: causal mask (qb == kb)
#pragma unroll
            for (int i = 0; i < 4; i++)
#pragma unroll
                for (int j = 0; j < 4; j++)
                    if (tx * 4 + j > ty * 4 + i) s[i][j] = -1e30f;
        }

        // prefetch V tile (global read, independent of smem hazards)
        float4 vv[4];
#pragma unroll
        for (int c = 0; c < 4; c++)
            vv[c] = *(const float4*)&V[base + (size_t)(kb + lrow) * HDIM + lk + c * 4];

        // online softmax
#pragma unroll
        for (int i = 0; i < 4; i++) {
            float rm = fmaxf(fmaxf(s[i][0], s[i][1]), fmaxf(s[i][2], s[i][3]));
            rm = red_max16(rm);
            const float mnew = fmaxf(mrow[i], rm);
            const float corr = __expf(mrow[i] - mnew);
            float rs = 0.f;
#pragma unroll
            for (int j = 0; j < 4; j++) {
                const float p = __expf(s[i][j] - mnew);
                s[i][j] = p;
                rs += p;
            }
            rs = red_sum16(rs);
            lsum[i] = lsum[i] * corr + rs;
            mrow[i] = mnew;
#pragma unroll
            for (int j = 0; j < 4; j++) acc[i][j] *= corr;
        }

        __syncthreads();   // all threads done reading KVs as K
#pragma unroll
        for (int c = 0; c < 4; c++)
            *(float4*)&KVs[lrow][lk + c * 4] = vv[c];  // V phase: [j][d]
#pragma unroll
        for (int i = 0; i < 4; i++)
            *(float4*)&Ps[ty * 4 + i][tx * 4] =
                make_float4(s[i][0], s[i][1], s[i][2], s[i][3]);
        __syncthreads();

        // acc += P @ V
#pragma unroll 4
        for (int jj = 0; jj < 64; jj++) {
            float4 v4 = *(const float4*)&KVs[jj][tx * 4];
            float vr[4] = {v4.x, v4.y, v4.z, v4.w};
#pragma unroll
            for (int i = 0; i < 4; i++) {
                const float p = Ps[ty * 4 + i][jj];
#pragma unroll
                for (int j = 0; j < 4; j++)
                    acc[i][j] = fmaf(p, vr[j], acc[i][j]);
            }
        }
    }

    // epilogue: normalize and scatter to [N, L, H*D]
    const int n = nh >> 4;
    const int h = nh & 15;
#pragma unroll
    for (int i = 0; i < 4; i++) {
        const float inv = 1.0f / lsum[i];
        const int q = qb + ty * 4 + i;
        float* dst = O + ((size_t)(n * LSEQ + q)) * EMBD + h * HDIM + tx * 4;
        *(float4*)dst = make_float4(acc[i][0] * inv, acc[i][1] * inv,
                                    acc[i][2] * inv, acc[i][3] * inv);
    }
}

extern "C" void kernel_launch(void* const* d_in, const int* in_sizes, int n_in,
                              void* d_out, int out_size)
{
    (void)in_sizes; (void)n_in; (void)out_size;
    const float* x  = (const float*)d_in[0];
    // d_in[1] = mask (unused)
    const float* Wq = (const float*)d_in[2];
    const float* Wk = (const float*)d_in[3];
    const float* Wv = (const float*)d_in[4];
    const float* gq = (const float*)d_in[5];
    const float* bq = (const float*)d_in[6];
    const float* gk = (const float*)d_in[7];
    const float* bk = (const float*)d_in[8];
    const float* Wo = (const float*)d_in[9];
    const float* bo = (const float*)d_in[10];
    float* out = (float*)d_out;

    float *qp, *kp, *vp, *ap;
    cudaGetSymbolAddress((void**)&qp, g_q);
    cudaGetSymbolAddress((void**)&kp, g_k);
    cudaGetSymbolAddress((void**)&vp, g_v);
    cudaGetSymbolAddress((void**)&ap, g_attn);

    dim3 gg(MROWS / 64, EMBD / 64);
    dim3 bb(256);
    gemm64<0><<<gg, bb>>>(x, Wq, gq, bq, nullptr, qp);
    gemm64<0><<<gg, bb>>>(x, Wk, gk, bk, nullptr, kp);
    gemm64<1><<<gg, bb>>>(x, Wv, nullptr, nullptr, nullptr, vp);

    attn_kernel<<<dim3(LSEQ / 64, NBATCH * NHEAD), 256>>>(qp, kp, vp, ap);

    gemm64<2><<<gg, bb>>>(ap, Wo, nullptr, nullptr, bo, out);
}

// round 4
// speedup vs baseline: 1.4962x; 1.4962x over previous
#include <cuda_runtime.h>
#include <cuda_bf16.h>
#include <cstdint>

// Problem constants
#define NBATCH 2
#define LSEQ   2048
#define EMBD   1024
#define NHEAD  16
#define HDIM   64
#define MROWS  (NBATCH * LSEQ)   // 4096

// Scratch (device globals: no allocation allowed)
__device__ float g_q[NBATCH * NHEAD * LSEQ * HDIM];
__device__ float g_k[NBATCH * NHEAD * LSEQ * HDIM];
__device__ float g_v[NBATCH * NHEAD * LSEQ * HDIM];
__device__ float g_attn[MROWS * EMBD];

// ---------------- GEMM config ----------------
#define BK 32
#define ASTR 36                        // bf16 elems per smem row (pad: conflict-free)
#define ARR_BYTES (128 * ASTR * 2)     // 9216
#define STAGE_BYTES_G (4 * ARR_BYTES)  // Ah | Al | Bh | Bl = 36864
#define GEMM_SMEM (2 * STAGE_BYTES_G)  // 73728 (also covers 128x132 f32 C tile: 67584)

__device__ __forceinline__ uint32_t pack2(__nv_bfloat16 a, __nv_bfloat16 b) {
    __nv_bfloat162 t = __halves2bfloat162(a, b);
    return *reinterpret_cast<uint32_t*>(&t);
}

__device__ __forceinline__ void mma16816(float* c, const uint32_t* a, const uint32_t* b) {
    asm volatile(
        "mma.sync.aligned.m16n8k16.row.col.f32.bf16.bf16.f32 "
        "{%0,%1,%2,%3}, {%4,%5,%6,%7}, {%8,%9}, {%0,%1,%2,%3};"
        : "+f"(c[0]), "+f"(c[1]), "+f"(c[2]), "+f"(c[3])
        : "r"(a[0]), "r"(a[1]), "r"(a[2]), "r"(a[3]), "r"(b[0]), "r"(b[1]));
}

// C = A @ W^T via 3x bf16-split MMA.
// MODE 0: per-head LayerNorm epilogue, head-major output [N,H,L,D]
// MODE 1: head-major output, no LN
// MODE 2: row-major output + bias
template <int MODE>
__global__ void __launch_bounds__(256, 2) bf16_gemm(
    const float* __restrict__ A, const float* __restrict__ W,
    const float* __restrict__ gamma, const float* __restrict__ beta,
    const float* __restrict__ bias, float* __restrict__ C)
{
    extern __shared__ char sm[];
    const int tid  = threadIdx.x;
    const int lane = tid & 31;
    const int wid  = tid >> 5;
    const int g    = lane >> 2;
    const int q    = lane & 3;
    const int warp_m = wid >> 2;   // 0..1
    const int warp_n = wid & 3;    // 0..3
    const int rb = blockIdx.x * 128;
    const int cb = blockIdx.y * 128;

    auto arr = [&](int s, int a) -> __nv_bfloat16* {
        return (__nv_bfloat16*)(sm + s * STAGE_BYTES_G + a * ARR_BYTES);
    };

    // Loaders: thread t covers tile row lr = t>>1, K-half lh = (t&1)*16
    const int lr = tid >> 1;
    const int lh = (tid & 1) * 16;
    const float* Ap = A + (size_t)(rb + lr) * EMBD + lh;
    const float* Wp = W + (size_t)(cb + lr) * EMBD + lh;

    float4 av[4], bv[4];
    auto ldg = [&](int kc) {
#pragma unroll
        for (int i = 0; i < 4; i++) {
            av[i] = *(const float4*)(Ap + kc * BK + 4 * i);
            bv[i] = *(const float4*)(Wp + kc * BK + 4 * i);
        }
    };
    auto sts = [&](int s) {
        __nv_bfloat16 *Ah = arr(s, 0), *Al = arr(s, 1), *Bh = arr(s, 2), *Bl = arr(s, 3);
#pragma unroll
        for (int i = 0; i < 4; i++) {
            const int off = lr * ASTR + lh + i * 4;
            {
                float4 a = av[i];
                __nv_bfloat16 h0 = __float2bfloat16(a.x), h1 = __float2bfloat16(a.y),
                              h2 = __float2bfloat16(a.z), h3 = __float2bfloat16(a.w);
                uint2 hv = make_uint2(pack2(h0, h1), pack2(h2, h3));
                uint2 lv = make_uint2(
                    pack2(__float2bfloat16(a.x - __bfloat162float(h0)),
                          __float2bfloat16(a.y - __bfloat162float(h1))),
                    pack2(__float2bfloat16(a.z - __bfloat162float(h2)),
                          __float2bfloat16(a.w - __bfloat162float(h3))));
                *(uint2*)(Ah + off) = hv;
                *(uint2*)(Al + off) = lv;
            }
            {
                float4 b = bv[i];
                __nv_bfloat16 h0 = __float2bfloat16(b.x), h1 = __float2bfloat16(b.y),
                              h2 = __float2bfloat16(b.z), h3 = __float2bfloat16(b.w);
                uint2 hv = make_uint2(pack2(h0, h1), pack2(h2, h3));
                uint2 lv = make_uint2(
                    pack2(__float2bfloat16(b.x - __bfloat162float(h0)),
                          __float2bfloat16(b.y - __bfloat162float(h1))),
                    pack2(__float2bfloat16(b.z - __bfloat162float(h2)),
                          __float2bfloat16(b.w - __bfloat162float(h3))));
                *(uint2*)(Bh + off) = hv;
                *(uint2*)(Bl + off) = lv;
            }
        }
    };

    float acc[4][4][4] = {};

    auto compute = [&](int s) {
        const __nv_bfloat16 *Ah = arr(s, 0), *Al = arr(s, 1),
                            *Bh = arr(s, 2), *Bl = arr(s, 3);
#pragma unroll
        for (int ks = 0; ks < 2; ks++) {
            const int kb = ks * 16 + q * 2;
            uint32_t ah[4][4], bh[4][2];
#pragma unroll
            for (int mf = 0; mf < 4; mf++) {
                const __nv_bfloat16* p = Ah + (warp_m * 64 + mf * 16 + g) * ASTR + kb;
                ah[mf][0] = *(const uint32_t*)p;
                ah[mf][1] = *(const uint32_t*)(p + 8 * ASTR);
                ah[mf][2] = *(const uint32_t*)(p + 8);
                ah[mf][3] = *(const uint32_t*)(p + 8 * ASTR + 8);
            }
#pragma unroll
            for (int nf = 0; nf < 4; nf++) {
                const __nv_bfloat16* p = Bh + (warp_n * 32 + nf * 8 + g) * ASTR + kb;
                bh[nf][0] = *(const uint32_t*)p;
                bh[nf][1] = *(const uint32_t*)(p + 8);
            }
            // hi * hi
#pragma unroll
            for (int mf = 0; mf < 4; mf++)
#pragma unroll
                for (int nf = 0; nf < 4; nf++)
                    mma16816(acc[mf][nf], ah[mf], bh[nf]);
            // hi * lo
#pragma unroll
            for (int nf = 0; nf < 4; nf++) {
                const __nv_bfloat16* p = Bl + (warp_n * 32 + nf * 8 + g) * ASTR + kb;
                uint32_t bl[2] = { *(const uint32_t*)p, *(const uint32_t*)(p + 8) };
#pragma unroll
                for (int mf = 0; mf < 4; mf++)
                    mma16816(acc[mf][nf], ah[mf], bl);
            }
            // lo * hi
#pragma unroll
            for (int mf = 0; mf < 4; mf++) {
                const __nv_bfloat16* p = Al + (warp_m * 64 + mf * 16 + g) * ASTR + kb;
                uint32_t al[4] = { *(const uint32_t*)p,
                                   *(const uint32_t*)(p + 8 * ASTR),
                                   *(const uint32_t*)(p + 8),
                                   *(const uint32_t*)(p + 8 * ASTR + 8) };
#pragma unroll
                for (int nf = 0; nf < 4; nf++)
                    mma16816(acc[mf][nf], al, bh[nf]);
            }
        }
    };

    ldg(0); sts(0);
    __syncthreads();
    for (int kc = 0; kc < EMBD / BK; kc++) {
        compute(kc & 1);
        if (kc + 1 < EMBD / BK) {
            ldg(kc + 1);
            sts((kc + 1) & 1);
        }
        __syncthreads();
    }

    // Stage C tile through smem (reuses stage buffers; all reads done after last sync)
    float* Ct = (float*)sm;   // [128][132]
#pragma unroll
    for (int mf = 0; mf < 4; mf++)
#pragma unroll
        for (int nf = 0; nf < 4; nf++) {
            const int r = warp_m * 64 + mf * 16 + g;
            const int c = warp_n * 32 + nf * 8 + q * 2;
            *(float2*)&Ct[r * 132 + c]       = make_float2(acc[mf][nf][0], acc[mf][nf][1]);
            *(float2*)&Ct[(r + 8) * 132 + c] = make_float2(acc[mf][nf][2], acc[mf][nf][3]);
        }
    __syncthreads();

    {
        const int row = tid >> 1;   // 0..127
        const int seg = tid & 1;    // 0..1 (64-col head segment)
        float f[64];
#pragma unroll
        for (int j = 0; j < 16; j++)
            *(float4*)&f[4 * j] = *(const float4*)&Ct[row * 132 + seg * 64 + 4 * j];

        if (MODE == 0) {
            float s = 0.f, s2 = 0.f;
#pragma unroll
            for (int j = 0; j < 64; j++) { s += f[j]; s2 += f[j] * f[j]; }
            const float mean = s * (1.0f / 64.0f);
            const float var  = s2 * (1.0f / 64.0f) - mean * mean;
            const float rstd = rsqrtf(var + 1e-5f);
#pragma unroll
            for (int j = 0; j < 64; j++)
                f[j] = (f[j] - mean) * rstd * __ldg(gamma + j) + __ldg(beta + j);
        }

        if (MODE == 0 || MODE == 1) {
            const int grow = rb + row;
            const int n = grow >> 11;
            const int l = grow & (LSEQ - 1);
            const int h = (cb >> 6) + seg;
            float* dst = C + ((size_t)((n * NHEAD + h) * LSEQ + l)) * HDIM;
#pragma unroll
            for (int j = 0; j < 16; j++) *(float4*)(dst + 4 * j) = *(float4*)&f[4 * j];
        } else {
            const int c0 = cb + seg * 64;
#pragma unroll
            for (int j = 0; j < 64; j++) f[j] += __ldg(bias + c0 + j);
            float* dst = C + (size_t)(rb + row) * EMBD + c0;
#pragma unroll
            for (int j = 0; j < 16; j++) *(float4*)(dst + 4 * j) = *(float4*)&f[4 * j];
        }
    }
}

// ------------------------- attention (unchanged, fp32 SIMT) -------------------------
__device__ __forceinline__ float red_sum16(float v) {
#pragma unroll
    for (int o = 8; o > 0; o >>= 1) v += __shfl_xor_sync(0xffffffffu, v, o, 16);
    return v;
}
__device__ __forceinline__ float red_max16(float v) {
#pragma unroll
    for (int o = 8; o > 0; o >>= 1) v = fmaxf(v, __shfl_xor_sync(0xffffffffu, v, o, 16));
    return v;
}

__global__ void __launch_bounds__(256) attn_kernel(
    const float* __restrict__ Q, const float* __restrict__ K,
    const float* __restrict__ V, float* __restrict__ O)
{
    __shared__ float Qs[64][64];
    __shared__ float KVs[64][64];
    __shared__ float Ps[64][64];

    const int tid = threadIdx.x;
    const int ty  = tid >> 4;
    const int tx  = tid & 15;
    const int nh  = blockIdx.y;
    const int qt  = gridDim.x - 1 - blockIdx.x;
    const int qb  = qt * 64;
    const size_t base = (size_t)nh * LSEQ * HDIM;

    const int lrow = tid >> 2;
    const int lk   = (tid & 3) << 4;

#pragma unroll
    for (int c = 0; c < 4; c++) {
        const int d0 = lk + c * 4;
        float4 qv = *(const float4*)&Q[base + (size_t)(qb + lrow) * HDIM + d0];
        Qs[d0 + 0][lrow] = qv.x; Qs[d0 + 1][lrow] = qv.y;
        Qs[d0 + 2][lrow] = qv.z; Qs[d0 + 3][lrow] = qv.w;
    }

    float acc[4][4] = {};
    float mrow[4] = {-1e30f, -1e30f, -1e30f, -1e30f};
    float lsum[4] = {0.f, 0.f, 0.f, 0.f};

    for (int kt = 0; kt <= qt; kt++) {
        const int kb = kt * 64;
        float4 kv[4];
#pragma unroll
        for (int c = 0; c < 4; c++)
            kv[c] = *(const float4*)&K[base + (size_t)(kb + lrow) * HDIM + lk + c * 4];
        __syncthreads();
#pragma unroll
        for (int c = 0; c < 4; c++) {
            const int d0 = lk + c * 4;
            KVs[d0 + 0][lrow] = kv[c].x; KVs[d0 + 1][lrow] = kv[c].y;
            KVs[d0 + 2][lrow] = kv[c].z; KVs[d0 + 3][lrow] = kv[c].w;
        }
        __syncthreads();

        float s[4][4] = {};
#pragma unroll 8
        for (int k = 0; k < 64; k++) {
            float4 q4 = *(const float4*)&Qs[k][ty * 4];
            float4 k4 = *(const float4*)&KVs[k][tx * 4];
            float qr[4] = {q4.x, q4.y, q4.z, q4.w};
            float kr[4] = {k4.x, k4.y, k4.z, k4.w};
#pragma unroll
            for (int i = 0; i < 4; i++)
#pragma unroll
                for (int j = 0; j < 4; j++)
                    s[i][j] = fmaf(qr[i], kr[j], s[i][j]);
        }

        if (kt == qt) {
#pragma unroll
            for (int i = 0; i < 4; i++)
#pragma unroll
                for (int j = 0; j < 4; j++)
                    if (tx * 4 + j > ty * 4 + i) s[i][j] = -1e30f;
        }

        float4 vv[4];
#pragma unroll
        for (int c = 0; c < 4; c++)
            vv[c] = *(const float4*)&V[base + (size_t)(kb + lrow) * HDIM + lk + c * 4];

#pragma unroll
        for (int i = 0; i < 4; i++) {
            float rm = fmaxf(fmaxf(s[i][0], s[i][1]), fmaxf(s[i][2], s[i][3]));
            rm = red_max16(rm);
            const float mnew = fmaxf(mrow[i], rm);
            const float corr = __expf(mrow[i] - mnew);
            float rs = 0.f;
#pragma unroll
            for (int j = 0; j < 4; j++) {
                const float p = __expf(s[i][j] - mnew);
                s[i][j] = p;
                rs += p;
            }
            rs = red_sum16(rs);
            lsum[i] = lsum[i] * corr + rs;
            mrow[i] = mnew;
#pragma unroll
            for (int j = 0; j < 4; j++) acc[i][j] *= corr;
        }

        __syncthreads();
#pragma unroll
        for (int c = 0; c < 4; c++)
            *(float4*)&KVs[lrow][lk + c * 4] = vv[c];
#pragma unroll
        for (int i = 0; i < 4; i++)
            *(float4*)&Ps[ty * 4 + i][tx * 4] =
                make_float4(s[i][0], s[i][1], s[i][2], s[i][3]);
        __syncthreads();

#pragma unroll 4
        for (int jj = 0; jj < 64; jj++) {
            float4 v4 = *(const float4*)&KVs[jj][tx * 4];
            float vr[4] = {v4.x, v4.y, v4.z, v4.w};
#pragma unroll
            for (int i = 0; i < 4; i++) {
                const float p = Ps[ty * 4 + i][jj];
#pragma unroll
                for (int j = 0; j < 4; j++)
                    acc[i][j] = fmaf(p, vr[j], acc[i][j]);
            }
        }
    }

    const int n = nh >> 4;
    const int h = nh & 15;
#pragma unroll
    for (int i = 0; i < 4; i++) {
        const float inv = 1.0f / lsum[i];
        const int q = qb + ty * 4 + i;
        float* dst = O + ((size_t)(n * LSEQ + q)) * EMBD + h * HDIM + tx * 4;
        *(float4*)dst = make_float4(acc[i][0] * inv, acc[i][1] * inv,
                                    acc[i][2] * inv, acc[i][3] * inv);
    }
}

// ------------------------- launch -------------------------
extern "C" void kernel_launch(void* const* d_in, const int* in_sizes, int n_in,
                              void* d_out, int out_size)
{
    (void)in_sizes; (void)n_in; (void)out_size;
    const float* x  = (const float*)d_in[0];
    const float* Wq = (const float*)d_in[2];
    const float* Wk = (const float*)d_in[3];
    const float* Wv = (const float*)d_in[4];
    const float* gq = (const float*)d_in[5];
    const float* bq = (const float*)d_in[6];
    const float* gk = (const float*)d_in[7];
    const float* bk = (const float*)d_in[8];
    const float* Wo = (const float*)d_in[9];
    const float* bo = (const float*)d_in[10];
    float* out = (float*)d_out;

    float *qp, *kp, *vp, *ap;
    cudaGetSymbolAddress((void**)&qp, g_q);
    cudaGetSymbolAddress((void**)&kp, g_k);
    cudaGetSymbolAddress((void**)&vp, g_v);
    cudaGetSymbolAddress((void**)&ap, g_attn);

    cudaFuncSetAttribute(bf16_gemm<0>, cudaFuncAttributeMaxDynamicSharedMemorySize, GEMM_SMEM);
    cudaFuncSetAttribute(bf16_gemm<1>, cudaFuncAttributeMaxDynamicSharedMemorySize, GEMM_SMEM);
    cudaFuncSetAttribute(bf16_gemm<2>, cudaFuncAttributeMaxDynamicSharedMemorySize, GEMM_SMEM);

    dim3 gg(MROWS / 128, EMBD / 128);
    bf16_gemm<0><<<gg, 256, GEMM_SMEM>>>(x, Wq, gq, bq, nullptr, qp);
    bf16_gemm<0><<<gg, 256, GEMM_SMEM>>>(x, Wk, gk, bk, nullptr, kp);
    bf16_gemm<1><<<gg, 256, GEMM_SMEM>>>(x, Wv, nullptr, nullptr, nullptr, vp);

    attn_kernel<<<dim3(LSEQ / 64, NBATCH * NHEAD), 256>>>(qp, kp, vp, ap);

    bf16_gemm<2><<<gg, 256, GEMM_SMEM>>>(ap, Wo, nullptr, nullptr, bo, out);
}

// round 5
// speedup vs baseline: 2.0147x; 1.3465x over previous
#include <cuda_runtime.h>
#include <cuda_bf16.h>
#include <cuda_fp16.h>
#include <cstdint>

// Problem constants
#define NBATCH 2
#define LSEQ   2048
#define EMBD   1024
#define NHEAD  16
#define HDIM   64
#define MROWS  (NBATCH * LSEQ)   // 4096

// Scratch (device globals: no allocation allowed)
__device__ float g_q[NBATCH * NHEAD * LSEQ * HDIM];
__device__ float g_k[NBATCH * NHEAD * LSEQ * HDIM];
__device__ float g_v[NBATCH * NHEAD * LSEQ * HDIM];
__device__ float g_attn[MROWS * EMBD];

__device__ __forceinline__ uint32_t smem_u32(const void* p) {
    uint32_t a;
    asm("{ .reg .u64 t; cvta.to.shared.u64 t, %1; cvt.u32.u64 %0, t; }"
        : "=r"(a) : "l"(p));
    return a;
}

// ---------------- GEMM (unchanged from R4, passing at ~126us each) ----------------
#define BK 32
#define ASTR 36
#define ARR_BYTES (128 * ASTR * 2)
#define STAGE_BYTES_G (4 * ARR_BYTES)
#define GEMM_SMEM (2 * STAGE_BYTES_G)

__device__ __forceinline__ uint32_t pack2(__nv_bfloat16 a, __nv_bfloat16 b) {
    __nv_bfloat162 t = __halves2bfloat162(a, b);
    return *reinterpret_cast<uint32_t*>(&t);
}

__device__ __forceinline__ void mma16816(float* c, const uint32_t* a, const uint32_t* b) {
    asm volatile(
        "mma.sync.aligned.m16n8k16.row.col.f32.bf16.bf16.f32 "
        "{%0,%1,%2,%3}, {%4,%5,%6,%7}, {%8,%9}, {%0,%1,%2,%3};"
        : "+f"(c[0]), "+f"(c[1]), "+f"(c[2]), "+f"(c[3])
        : "r"(a[0]), "r"(a[1]), "r"(a[2]), "r"(a[3]), "r"(b[0]), "r"(b[1]));
}

template <int MODE>
__global__ void __launch_bounds__(256, 2) bf16_gemm(
    const float* __restrict__ A, const float* __restrict__ W,
    const float* __restrict__ gamma, const float* __restrict__ beta,
    const float* __restrict__ bias, float* __restrict__ C)
{
    extern __shared__ char sm[];
    const int tid  = threadIdx.x;
    const int lane = tid & 31;
    const int wid  = tid >> 5;
    const int g    = lane >> 2;
    const int q    = lane & 3;
    const int warp_m = wid >> 2;
    const int warp_n = wid & 3;
    const int rb = blockIdx.x * 128;
    const int cb = blockIdx.y * 128;

    auto arr = [&](int s, int a) -> __nv_bfloat16* {
        return (__nv_bfloat16*)(sm + s * STAGE_BYTES_G + a * ARR_BYTES);
    };

    const int lr = tid >> 1;
    const int lh = (tid & 1) * 16;
    const float* Ap = A + (size_t)(rb + lr) * EMBD + lh;
    const float* Wp = W + (size_t)(cb + lr) * EMBD + lh;

    float4 av[4], bv[4];
    auto ldg = [&](int kc) {
#pragma unroll
        for (int i = 0; i < 4; i++) {
            av[i] = *(const float4*)(Ap + kc * BK + 4 * i);
            bv[i] = *(const float4*)(Wp + kc * BK + 4 * i);
        }
    };
    auto sts = [&](int s) {
        __nv_bfloat16 *Ah = arr(s, 0), *Al = arr(s, 1), *Bh = arr(s, 2), *Bl = arr(s, 3);
#pragma unroll
        for (int i = 0; i < 4; i++) {
            const int off = lr * ASTR + lh + i * 4;
            {
                float4 a = av[i];
                __nv_bfloat16 h0 = __float2bfloat16(a.x), h1 = __float2bfloat16(a.y),
                              h2 = __float2bfloat16(a.z), h3 = __float2bfloat16(a.w);
                *(uint2*)(Ah + off) = make_uint2(pack2(h0, h1), pack2(h2, h3));
                *(uint2*)(Al + off) = make_uint2(
                    pack2(__float2bfloat16(a.x - __bfloat162float(h0)),
                          __float2bfloat16(a.y - __bfloat162float(h1))),
                    pack2(__float2bfloat16(a.z - __bfloat162float(h2)),
                          __float2bfloat16(a.w - __bfloat162float(h3))));
            }
            {
                float4 b = bv[i];
                __nv_bfloat16 h0 = __float2bfloat16(b.x), h1 = __float2bfloat16(b.y),
                              h2 = __float2bfloat16(b.z), h3 = __float2bfloat16(b.w);
                *(uint2*)(Bh + off) = make_uint2(pack2(h0, h1), pack2(h2, h3));
                *(uint2*)(Bl + off) = make_uint2(
                    pack2(__float2bfloat16(b.x - __bfloat162float(h0)),
                          __float2bfloat16(b.y - __bfloat162float(h1))),
                    pack2(__float2bfloat16(b.z - __bfloat162float(h2)),
                          __float2bfloat16(b.w - __bfloat162float(h3))));
            }
        }
    };

    float acc[4][4][4] = {};

    auto compute = [&](int s) {
        const __nv_bfloat16 *Ah = arr(s, 0), *Al = arr(s, 1),
                            *Bh = arr(s, 2), *Bl = arr(s, 3);
#pragma unroll
        for (int ks = 0; ks < 2; ks++) {
            const int kb = ks * 16 + q * 2;
            uint32_t ah[4][4], bh[4][2];
#pragma unroll
            for (int mf = 0; mf < 4; mf++) {
                const __nv_bfloat16* p = Ah + (warp_m * 64 + mf * 16 + g) * ASTR + kb;
                ah[mf][0] = *(const uint32_t*)p;
                ah[mf][1] = *(const uint32_t*)(p + 8 * ASTR);
                ah[mf][2] = *(const uint32_t*)(p + 8);
                ah[mf][3] = *(const uint32_t*)(p + 8 * ASTR + 8);
            }
#pragma unroll
            for (int nf = 0; nf < 4; nf++) {
                const __nv_bfloat16* p = Bh + (warp_n * 32 + nf * 8 + g) * ASTR + kb;
                bh[nf][0] = *(const uint32_t*)p;
                bh[nf][1] = *(const uint32_t*)(p + 8);
            }
#pragma unroll
            for (int mf = 0; mf < 4; mf++)
#pragma unroll
                for (int nf = 0; nf < 4; nf++)
                    mma16816(acc[mf][nf], ah[mf], bh[nf]);
#pragma unroll
            for (int nf = 0; nf < 4; nf++) {
                const __nv_bfloat16* p = Bl + (warp_n * 32 + nf * 8 + g) * ASTR + kb;
                uint32_t bl[2] = { *(const uint32_t*)p, *(const uint32_t*)(p + 8) };
#pragma unroll
                for (int mf = 0; mf < 4; mf++)
                    mma16816(acc[mf][nf], ah[mf], bl);
            }
#pragma unroll
            for (int mf = 0; mf < 4; mf++) {
                const __nv_bfloat16* p = Al + (warp_m * 64 + mf * 16 + g) * ASTR + kb;
                uint32_t al[4] = { *(const uint32_t*)p,
                                   *(const uint32_t*)(p + 8 * ASTR),
                                   *(const uint32_t*)(p + 8),
                                   *(const uint32_t*)(p + 8 * ASTR + 8) };
#pragma unroll
                for (int nf = 0; nf < 4; nf++)
                    mma16816(acc[mf][nf], al, bh[nf]);
            }
        }
    };

    ldg(0); sts(0);
    __syncthreads();
    for (int kc = 0; kc < EMBD / BK; kc++) {
        compute(kc & 1);
        if (kc + 1 < EMBD / BK) {
            ldg(kc + 1);
            sts((kc + 1) & 1);
        }
        __syncthreads();
    }

    float* Ct = (float*)sm;   // [128][132]
#pragma unroll
    for (int mf = 0; mf < 4; mf++)
#pragma unroll
        for (int nf = 0; nf < 4; nf++) {
            const int r = warp_m * 64 + mf * 16 + g;
            const int c = warp_n * 32 + nf * 8 + q * 2;
            *(float2*)&Ct[r * 132 + c]       = make_float2(acc[mf][nf][0], acc[mf][nf][1]);
            *(float2*)&Ct[(r + 8) * 132 + c] = make_float2(acc[mf][nf][2], acc[mf][nf][3]);
        }
    __syncthreads();

    {
        const int row = tid >> 1;
        const int seg = tid & 1;
        float f[64];
#pragma unroll
        for (int j = 0; j < 16; j++)
            *(float4*)&f[4 * j] = *(const float4*)&Ct[row * 132 + seg * 64 + 4 * j];

        if (MODE == 0) {
            float s = 0.f, s2 = 0.f;
#pragma unroll
            for (int j = 0; j < 64; j++) { s += f[j]; s2 += f[j] * f[j]; }
            const float mean = s * (1.0f / 64.0f);
            const float var  = s2 * (1.0f / 64.0f) - mean * mean;
            const float rstd = rsqrtf(var + 1e-5f);
#pragma unroll
            for (int j = 0; j < 64; j++)
                f[j] = (f[j] - mean) * rstd * __ldg(gamma + j) + __ldg(beta + j);
        }

        if (MODE == 0 || MODE == 1) {
            const int grow = rb + row;
            const int n = grow >> 11;
            const int l = grow & (LSEQ - 1);
            const int h = (cb >> 6) + seg;
            float* dst = C + ((size_t)((n * NHEAD + h) * LSEQ + l)) * HDIM;
#pragma unroll
            for (int j = 0; j < 16; j++) *(float4*)(dst + 4 * j) = *(float4*)&f[4 * j];
        } else {
            const int c0 = cb + seg * 64;
#pragma unroll
            for (int j = 0; j < 64; j++) f[j] += __ldg(bias + c0 + j);
            float* dst = C + (size_t)(rb + row) * EMBD + c0;
#pragma unroll
            for (int j = 0; j < 16; j++) *(float4*)(dst + 4 * j) = *(float4*)&f[4 * j];
        }
    }
}

// ---------------- Attention v2: fp16 split-precision mma.sync ----------------
#define APAD 72   // half stride per row: ldmatrix reads land on all 32 banks

#define LDSM_X4(r0, r1, r2, r3, addr) \
    asm volatile("ldmatrix.sync.aligned.m8n8.x4.shared.b16 {%0,%1,%2,%3}, [%4];" \
        : "=r"(r0), "=r"(r1), "=r"(r2), "=r"(r3) : "r"(addr))
#define LDSM_X2(r0, r1, addr) \
    asm volatile("ldmatrix.sync.aligned.m8n8.x2.shared.b16 {%0,%1}, [%2];" \
        : "=r"(r0), "=r"(r1) : "r"(addr))
#define LDSM_X2T(r0, r1, addr) \
    asm volatile("ldmatrix.sync.aligned.m8n8.x2.trans.shared.b16 {%0,%1}, [%2];" \
        : "=r"(r0), "=r"(r1) : "r"(addr))

__device__ __forceinline__ void mma_f16(float* c, const uint32_t* a, const uint32_t* b) {
    asm volatile(
        "mma.sync.aligned.m16n8k16.row.col.f32.f16.f16.f32 "
        "{%0,%1,%2,%3}, {%4,%5,%6,%7}, {%8,%9}, {%0,%1,%2,%3};"
        : "+f"(c[0]), "+f"(c[1]), "+f"(c[2]), "+f"(c[3])
        : "r"(a[0]), "r"(a[1]), "r"(a[2]), "r"(a[3]), "r"(b[0]), "r"(b[1]));
}

__device__ __forceinline__ uint32_t packh2(float a, float b) {
    __half2 h = __floats2half2_rn(a, b);
    return *reinterpret_cast<uint32_t*>(&h);
}

// split float4 -> hi/lo half quads
__device__ __forceinline__ void split4(float4 v, uint2& hi, uint2& lo) {
    __half h0 = __float2half_rn(v.x), h1 = __float2half_rn(v.y),
           h2 = __float2half_rn(v.z), h3 = __float2half_rn(v.w);
    hi = make_uint2(packh2(__half2float(h0), __half2float(h1)) /*placeholder*/, 0);
    // exact pack of the fp16 values:
    __half2 p01 = __halves2half2(h0, h1), p23 = __halves2half2(h2, h3);
    hi = make_uint2(*(uint32_t*)&p01, *(uint32_t*)&p23);
    lo = make_uint2(packh2(v.x - __half2float(h0), v.y - __half2float(h1)),
                    packh2(v.z - __half2float(h2), v.w - __half2float(h3)));
}

__global__ void __launch_bounds__(128) attn_mma(
    const float* __restrict__ Q, const float* __restrict__ K,
    const float* __restrict__ V, float* __restrict__ O)
{
    __shared__ __half Kh[64 * APAD], Kl[64 * APAD], Vh[64 * APAD], Vl[64 * APAD];

    const int tid  = threadIdx.x;
    const int lane = tid & 31;
    const int wid  = tid >> 5;      // 0..3
    const int g    = lane >> 2;     // 0..7
    const int t    = lane & 3;      // 0..3
    const int nh   = blockIdx.y;
    const int qt   = gridDim.x - 1 - blockIdx.x;   // heavy tiles first
    const int qb   = qt * 64;
    const size_t base = (size_t)nh * LSEQ * HDIM;

    const int lr = tid >> 1;            // 0..63 (tile row for loads)
    const int lc = (tid & 1) * 32;      // col half

    // --- stage Q tile into Kh/Kl, pull fragments into registers ---
    {
#pragma unroll
        for (int i = 0; i < 8; i++) {
            float4 v = *(const float4*)&Q[base + (size_t)(qb + lr) * HDIM + lc + 4 * i];
            uint2 hi, lo;
            split4(v, hi, lo);
            *(uint2*)&Kh[lr * APAD + lc + 4 * i] = hi;
            *(uint2*)&Kl[lr * APAD + lc + 4 * i] = lo;
        }
    }
    __syncthreads();

    uint32_t qh[4][4], ql[4][4];
    {
        const int frow = wid * 16 + (lane & 15);
        const int fcol8 = (lane >> 4) << 3;
#pragma unroll
        for (int kc = 0; kc < 4; kc++) {
            uint32_t a0 = smem_u32(&Kh[frow * APAD + kc * 16 + fcol8]);
            LDSM_X4(qh[kc][0], qh[kc][1], qh[kc][2], qh[kc][3], a0);
            uint32_t a1 = smem_u32(&Kl[frow * APAD + kc * 16 + fcol8]);
            LDSM_X4(ql[kc][0], ql[kc][1], ql[kc][2], ql[kc][3], a1);
        }
    }

    float oc[8][4] = {};
    float m0 = -1e30f, m1 = -1e30f, l0 = 0.f, l1 = 0.f;

    // fragment addresses (precompute lane components)
    const int kfr = lane & 7;                 // K frag row-within-8
    const int kfc = ((lane & 15) >> 3) << 3;  // K frag col offset 0/8
    const int vfr = lane & 15;                // V frag row-within-16

    for (int kt = 0; kt <= qt; kt++) {
        const int kb = kt * 64;
        // load K/V fp32 tiles into registers
        float4 kr[8], vr[8];
#pragma unroll
        for (int i = 0; i < 8; i++) {
            kr[i] = *(const float4*)&K[base + (size_t)(kb + lr) * HDIM + lc + 4 * i];
            vr[i] = *(const float4*)&V[base + (size_t)(kb + lr) * HDIM + lc + 4 * i];
        }
        __syncthreads();   // previous iteration's ldmatrix reads done (and Q frags, iter 0)
#pragma unroll
        for (int i = 0; i < 8; i++) {
            uint2 hi, lo;
            split4(kr[i], hi, lo);
            *(uint2*)&Kh[lr * APAD + lc + 4 * i] = hi;
            *(uint2*)&Kl[lr * APAD + lc + 4 * i] = lo;
            split4(vr[i], hi, lo);
            *(uint2*)&Vh[lr * APAD + lc + 4 * i] = hi;
            *(uint2*)&Vl[lr * APAD + lc + 4 * i] = lo;
        }
        __syncthreads();

        // ---- S = Q K^T (3-product split) ----
        float sc[8][4] = {};
#pragma unroll
        for (int kc = 0; kc < 4; kc++) {
#pragma unroll
            for (int nf = 0; nf < 8; nf++) {
                uint32_t bh[2], bl[2];
                uint32_t ah_addr = smem_u32(&Kh[(nf * 8 + kfr) * APAD + kc * 16 + kfc]);
                LDSM_X2(bh[0], bh[1], ah_addr);
                uint32_t al_addr = smem_u32(&Kl[(nf * 8 + kfr) * APAD + kc * 16 + kfc]);
                LDSM_X2(bl[0], bl[1], al_addr);
                mma_f16(sc[nf], qh[kc], bh);
                mma_f16(sc[nf], qh[kc], bl);
                mma_f16(sc[nf], ql[kc], bh);
            }
        }

        // ---- causal mask on diagonal tile ----
        if (kt == qt) {
            const int r0 = wid * 16 + g;
            const int r1 = r0 + 8;
#pragma unroll
            for (int nf = 0; nf < 8; nf++) {
                const int c0 = nf * 8 + 2 * t;
                if (c0     > r0) sc[nf][0] = -1e30f;
                if (c0 + 1 > r0) sc[nf][1] = -1e30f;
                if (c0     > r1) sc[nf][2] = -1e30f;
                if (c0 + 1 > r1) sc[nf][3] = -1e30f;
            }
        }

        // ---- online softmax (rows g and g+8 of this warp's 16) ----
        {
            float rm0 = -1e30f, rm1 = -1e30f;
#pragma unroll
            for (int nf = 0; nf < 8; nf++) {
                rm0 = fmaxf(rm0, fmaxf(sc[nf][0], sc[nf][1]));
                rm1 = fmaxf(rm1, fmaxf(sc[nf][2], sc[nf][3]));
            }
            rm0 = fmaxf(rm0, __shfl_xor_sync(0xffffffffu, rm0, 1));
            rm0 = fmaxf(rm0, __shfl_xor_sync(0xffffffffu, rm0, 2));
            rm1 = fmaxf(rm1, __shfl_xor_sync(0xffffffffu, rm1, 1));
            rm1 = fmaxf(rm1, __shfl_xor_sync(0xffffffffu, rm1, 2));

            const float mn0 = fmaxf(m0, rm0), mn1 = fmaxf(m1, rm1);
            const float cr0 = __expf(m0 - mn0), cr1 = __expf(m1 - mn1);
            float rs0 = 0.f, rs1 = 0.f;
#pragma unroll
            for (int nf = 0; nf < 8; nf++) {
                sc[nf][0] = __expf(sc[nf][0] - mn0);
                sc[nf][1] = __expf(sc[nf][1] - mn0);
                sc[nf][2] = __expf(sc[nf][2] - mn1);
                sc[nf][3] = __expf(sc[nf][3] - mn1);
                rs0 += sc[nf][0] + sc[nf][1];
                rs1 += sc[nf][2] + sc[nf][3];
            }
            rs0 += __shfl_xor_sync(0xffffffffu, rs0, 1);
            rs0 += __shfl_xor_sync(0xffffffffu, rs0, 2);
            rs1 += __shfl_xor_sync(0xffffffffu, rs1, 1);
            rs1 += __shfl_xor_sync(0xffffffffu, rs1, 2);

            l0 = l0 * cr0 + rs0; l1 = l1 * cr1 + rs1;
            m0 = mn0; m1 = mn1;
#pragma unroll
            for (int nf = 0; nf < 8; nf++) {
                oc[nf][0] *= cr0; oc[nf][1] *= cr0;
                oc[nf][2] *= cr1; oc[nf][3] *= cr1;
            }
        }

        // ---- O += P V (3-product split; P frags from S accumulators) ----
#pragma unroll
        for (int kc = 0; kc < 4; kc++) {
            uint32_t pah[4], pal[4];
            {
                const float* e0 = sc[2 * kc];
                const float* e1 = sc[2 * kc + 1];
                __half h00 = __float2half_rn(e0[0]), h01 = __float2half_rn(e0[1]);
                __half h02 = __float2half_rn(e0[2]), h03 = __float2half_rn(e0[3]);
                __half h10 = __float2half_rn(e1[0]), h11 = __float2half_rn(e1[1]);
                __half h12 = __float2half_rn(e1[2]), h13 = __float2half_rn(e1[3]);
                __half2 p;
                p = __halves2half2(h00, h01); pah[0] = *(uint32_t*)&p;
                p = __halves2half2(h02, h03); pah[1] = *(uint32_t*)&p;
                p = __halves2half2(h10, h11); pah[2] = *(uint32_t*)&p;
                p = __halves2half2(h12, h13); pah[3] = *(uint32_t*)&p;
                pal[0] = packh2(e0[0] - __half2float(h00), e0[1] - __half2float(h01));
                pal[1] = packh2(e0[2] - __half2float(h02), e0[3] - __half2float(h03));
                pal[2] = packh2(e1[0] - __half2float(h10), e1[1] - __half2float(h11));
                pal[3] = packh2(e1[2] - __half2float(h12), e1[3] - __half2float(h13));
            }
#pragma unroll
            for (int nf = 0; nf < 8; nf++) {
                uint32_t vh[2], vl[2];
                uint32_t vh_addr = smem_u32(&Vh[(kc * 16 + vfr) * APAD + nf * 8]);
                LDSM_X2T(vh[0], vh[1], vh_addr);
                uint32_t vl_addr = smem_u32(&Vl[(kc * 16 + vfr) * APAD + nf * 8]);
                LDSM_X2T(vl[0], vl[1], vl_addr);
                mma_f16(oc[nf], pah, vh);
                mma_f16(oc[nf], pal, vh);
                mma_f16(oc[nf], pah, vl);
            }
        }
    }

    // ---- epilogue: normalize, scatter to [N, L, H*D] ----
    const float inv0 = 1.0f / l0, inv1 = 1.0f / l1;
    const int n = nh >> 4;
    const int h = nh & 15;
    const int r0 = qb + wid * 16 + g;
    const int r1 = r0 + 8;
#pragma unroll
    for (int nf = 0; nf < 8; nf++) {
        const int col = h * HDIM + nf * 8 + 2 * t;
        *(float2*)&O[(size_t)(n * LSEQ + r0) * EMBD + col] =
            make_float2(oc[nf][0] * inv0, oc[nf][1] * inv0);
        *(float2*)&O[(size_t)(n * LSEQ + r1) * EMBD + col] =
            make_float2(oc[nf][2] * inv1, oc[nf][3] * inv1);
    }
}

// ------------------------- launch -------------------------
extern "C" void kernel_launch(void* const* d_in, const int* in_sizes, int n_in,
                              void* d_out, int out_size)
{
    (void)in_sizes; (void)n_in; (void)out_size;
    const float* x  = (const float*)d_in[0];
    const float* Wq = (const float*)d_in[2];
    const float* Wk = (const float*)d_in[3];
    const float* Wv = (const float*)d_in[4];
    const float* gq = (const float*)d_in[5];
    const float* bq = (const float*)d_in[6];
    const float* gk = (const float*)d_in[7];
    const float* bk = (const float*)d_in[8];
    const float* Wo = (const float*)d_in[9];
    const float* bo = (const float*)d_in[10];
    float* out = (float*)d_out;

    float *qp, *kp, *vp, *ap;
    cudaGetSymbolAddress((void**)&qp, g_q);
    cudaGetSymbolAddress((void**)&kp, g_k);
    cudaGetSymbolAddress((void**)&vp, g_v);
    cudaGetSymbolAddress((void**)&ap, g_attn);

    cudaFuncSetAttribute(bf16_gemm<0>, cudaFuncAttributeMaxDynamicSharedMemorySize, GEMM_SMEM);
    cudaFuncSetAttribute(bf16_gemm<1>, cudaFuncAttributeMaxDynamicSharedMemorySize, GEMM_SMEM);
    cudaFuncSetAttribute(bf16_gemm<2>, cudaFuncAttributeMaxDynamicSharedMemorySize, GEMM_SMEM);

    dim3 gg(MROWS / 128, EMBD / 128);
    bf16_gemm<0><<<gg, 256, GEMM_SMEM>>>(x, Wq, gq, bq, nullptr, qp);
    bf16_gemm<0><<<gg, 256, GEMM_SMEM>>>(x, Wk, gk, bk, nullptr, kp);
    bf16_gemm<1><<<gg, 256, GEMM_SMEM>>>(x, Wv, nullptr, nullptr, nullptr, vp);

    attn_mma<<<dim3(LSEQ / 64, NBATCH * NHEAD), 128>>>(qp, kp, vp, ap);

    bf16_gemm<2><<<gg, 256, GEMM_SMEM>>>(ap, Wo, nullptr, nullptr, bo, out);
}